// round 6
// baseline (speedup 1.0000x reference)
#include <cuda_runtime.h>
#include <cstdint>

// Problem constants (from reference)
#define F_FEATS   8
#define BL        81920u             // 4096*20 ids per feature
#define VOCAB     1000000u
#define DIM_V4    32                 // 128 floats = 32 float4 per row
#define N_ROWS    655360u            // F_FEATS * BL output rows
#define ROWS_PER_WARP 16
#define WARPS_PER_BLOCK 4

// Each warp handles 16 consecutive output rows:
//   - 16 uniform id loads (four L1 sectors, broadcast)
//   - slots kept as u32 to limit register pressure
//   - 16 back-to-back gather LDG.128 (MLP=16, 8KB in flight per warp)
//   - 16 contiguous streaming STG.128 (__stcs: evict-first, keep L2 for table)
// Output feature f sources input feature f^4 (split_sizes=(4,4), order=(1,0)).
__global__ void __launch_bounds__(WARPS_PER_BLOCK * 32)
emb_gather_kernel(const int* __restrict__ values,
                  const float4* __restrict__ table,
                  float4* __restrict__ out)
{
    const unsigned lane   = threadIdx.x & 31u;
    const unsigned warpId = blockIdx.x * WARPS_PER_BLOCK + (threadIdx.x >> 5);
    const unsigned row0   = warpId * ROWS_PER_WARP;
    if (row0 >= N_ROWS) return;

    // 32-bit const division: f = row0 / 81920 (group never crosses a feature
    // edge; 81920 % 16 == 0)
    const unsigned f     = row0 / BL;            // umulhi+shift, cheap
    const unsigned i0    = row0 - f * BL;
    const unsigned src_f = f ^ 4u;               // feature-block permutation

    const int* __restrict__ vptr = values + (size_t)src_f * BL + i0;

    // Phase 1: fetch all 16 slots (consecutive ids -> broadcast loads).
    unsigned slot[ROWS_PER_WARP];
    #pragma unroll
    for (int k = 0; k < ROWS_PER_WARP; k++)
        slot[k] = (unsigned)__ldg(vptr + k) % VOCAB;

    // Phase 2+3: two half-batches of 8 to bound register pressure while
    // keeping >=8 gathers in flight at all times.
    const float4* __restrict__ base = table + lane;
    float4* __restrict__ dst = out + (size_t)row0 * DIM_V4 + lane;

    float4 r[ROWS_PER_WARP / 2];
    #pragma unroll
    for (int k = 0; k < 8; k++)
        r[k] = __ldg(base + (size_t)slot[k] * DIM_V4);
    #pragma unroll
    for (int k = 0; k < 8; k++)
        __stcs(dst + k * DIM_V4, r[k]);
    #pragma unroll
    for (int k = 0; k < 8; k++)
        r[k] = __ldg(base + (size_t)slot[8 + k] * DIM_V4);
    #pragma unroll
    for (int k = 0; k < 8; k++)
        __stcs(dst + (8 + k) * DIM_V4, r[k]);
}

extern "C" void kernel_launch(void* const* d_in, const int* in_sizes, int n_in,
                              void* d_out, int out_size)
{
    const int*    values = (const int*)d_in[0];
    const float4* table  = (const float4*)d_in[1];
    float4*       out    = (float4*)d_out;

    // 4 warps/block * 16 rows/warp = 64 rows per block; exact cover
    const int blocks = N_ROWS / (WARPS_PER_BLOCK * ROWS_PER_WARP);   // 10240
    emb_gather_kernel<<<blocks, WARPS_PER_BLOCK * 32>>>(values, table, out);
}

// round 7
// speedup vs baseline: 1.0032x; 1.0032x over previous
#include <cuda_runtime.h>
#include <cstdint>

// Problem constants (from reference)
#define F_FEATS   8
#define BL        81920u             // 4096*20 ids per feature
#define VOCAB     1000000u
#define DIM_V4    32                 // 128 floats = 32 float4 per row
#define N_ROWS    655360u            // F_FEATS * BL output rows
#define ROWS_PER_WARP 8

// Best-measured configuration (R5) + vectorized id fetch.
// Each warp handles 8 consecutive output rows:
//   - 2x int4 uniform id loads (one L1 sector, broadcast)
//   - slots kept as u32 to limit register pressure (32 regs, occ ~84%)
//   - 8 back-to-back gather LDG.128 (MLP=8, 4KB in flight per warp)
//   - 8 contiguous streaming STG.128 (__stcs: evict-first, keep L2 for table)
// Output feature f sources input feature f^4 (split_sizes=(4,4), order=(1,0)).
__global__ void __launch_bounds__(256)
emb_gather_kernel(const int* __restrict__ values,
                  const float4* __restrict__ table,
                  float4* __restrict__ out)
{
    const unsigned lane   = threadIdx.x & 31u;
    const unsigned warpId = blockIdx.x * 8u + (threadIdx.x >> 5);
    const unsigned row0   = warpId * ROWS_PER_WARP;
    if (row0 >= N_ROWS) return;

    // 32-bit const division: f = row0 / 81920 (group never crosses a feature
    // edge; 81920 % 8 == 0, and row0 is 8-aligned -> id block is 16B-aligned)
    const unsigned f     = row0 / BL;            // umulhi+shift, cheap
    const unsigned i0    = row0 - f * BL;
    const unsigned src_f = f ^ 4u;               // feature-block permutation

    const int4* __restrict__ vptr =
        (const int4*)(values + (size_t)src_f * BL + i0);

    // Phase 1: fetch all 8 slots with two vector loads (broadcast).
    const int4 ida = __ldg(vptr);
    const int4 idb = __ldg(vptr + 1);
    unsigned slot[ROWS_PER_WARP] = {
        (unsigned)ida.x % VOCAB, (unsigned)ida.y % VOCAB,
        (unsigned)ida.z % VOCAB, (unsigned)ida.w % VOCAB,
        (unsigned)idb.x % VOCAB, (unsigned)idb.y % VOCAB,
        (unsigned)idb.z % VOCAB, (unsigned)idb.w % VOCAB };

    // Phase 2: issue all gathers back-to-back (MLP=8, 4KB in flight/warp).
    const float4* __restrict__ base = table + lane;
    float4 r[ROWS_PER_WARP];
    #pragma unroll
    for (int k = 0; k < ROWS_PER_WARP; k++)
        r[k] = __ldg(base + (size_t)slot[k] * DIM_V4);

    // Phase 3: 4KB contiguous streaming store (evict-first; don't pollute L2)
    float4* __restrict__ dst = out + (size_t)row0 * DIM_V4 + lane;
    #pragma unroll
    for (int k = 0; k < ROWS_PER_WARP; k++)
        __stcs(dst + k * DIM_V4, r[k]);
}

extern "C" void kernel_launch(void* const* d_in, const int* in_sizes, int n_in,
                              void* d_out, int out_size)
{
    const int*    values = (const int*)d_in[0];
    const float4* table  = (const float4*)d_in[1];
    float4*       out    = (float4*)d_out;

    // 8 warps/block * 8 rows/warp = 64 rows per block; exact cover
    const int blocks = N_ROWS / (8 * ROWS_PER_WARP);   // 10240
    emb_gather_kernel<<<blocks, 256>>>(values, table, out);
}